// round 8
// baseline (speedup 1.0000x reference)
#include <cuda_runtime.h>
#include <cstdint>

// MultiLIF: I[B=32, L=2048, K=512] -> (spikes[B,L,K], spike_series[B,L,K])
// d_out: spikes (B*L*K floats) then spike_series.
//
// R8 vs R7 (105us): per-warp ILP. R7 warps issue ~20 instr but stall ~70cyc
// per step (1 warp/SMSP, nothing overlaps the per-op latencies). Now each
// thread owns 2 adjacent neurons (float2): two independent recurrence chains
// interleave in one warp, and LDG.64/STG.64 halve memory instructions per
// neuron. Keeps R7's wins: 128 SMs (128 blocks x 64 thr), speculative reset,
// deep ring (NBUF=8 x UNROLL=4 -> 28-step load lead). Per-lane arithmetic
// identical to R7 -> rel_err 0.

static constexpr int B_ = 32;
static constexpr int L_ = 2048;
static constexpr int K_ = 512;
static constexpr int K2 = K_ / 2;            // 256 float2 per timestep row
static constexpr int NTHREADS = B_ * K2;     // 8192
static constexpr int UNROLL = 4;             // timesteps per batch
static constexpr int NBUF = 8;               // ring depth
static constexpr int NBATCH = L_ / UNROLL;   // 512
static constexpr int STRIDE2 = UNROLL * K2;  // float2 elems per batch

__device__ __forceinline__ float div_const_rn(float x, float b, float y)
{
    // Markstein: correctly-rounded RN(x/b), y = RN(1/b). Branch-free;
    // == __fdiv_rn for all values reachable here.
    float q0 = __fmul_rn(x, y);
    float r  = __fmaf_rn(-b, q0, x);
    return __fmaf_rn(r, y, q0);
}

__device__ __forceinline__ void lif_lane(float It, float c2,
                                         float& uv, bool& fire,
                                         float& a, float& n, float& s_out)
{
    float th = 1.0f + 1.5f * a;
    float uA = (uv - div_const_rn(uv, 20.0f, 0.05f)) + It;
    float uB = c2 + It;
    float un = fire ? uB : uA;
    bool f = (un >= th);
    float s = f ? 1.0f : 0.0f;
    n = n + s;
    a = (a - div_const_rn(a, 100.0f, 0.01f)) + s;
    uv = un; fire = f;
    s_out = s;
}

__global__ __launch_bounds__(64, 1)
void MultiLIF_kernel(const float2* __restrict__ I,
                     float2* __restrict__ spikes,
                     float2* __restrict__ series)
{
    int gid = blockIdx.x * blockDim.x + threadIdx.x;   // 0..8191
    int b  = gid >> 8;            // /256
    int kp = gid & (K2 - 1);

    int64_t base = (int64_t)b * L_ * K2 + kp;
    const float2* ip = I + base;
    float2* sp = spikes + base;
    float2* np = series + base;

    // fire-path constant: exact decay of v=-0.5 with the same rounded ops
    const float c2 = -0.5f - div_const_rn(-0.5f, 20.0f, 0.05f);

    float2 buf[NBUF][UNROLL];

    // prologue: batches 0..NBUF-2 into slots 0..NBUF-2
#pragma unroll
    for (int p = 0; p < NBUF - 1; p++) {
#pragma unroll
        for (int u = 0; u < UNROLL; u++)
            buf[p][u] = __ldcs(ip + (int64_t)(p * UNROLL + u) * K2);
    }

    float2 uv = {0.f, 0.f}, a = {0.f, 0.f}, n = {0.f, 0.f};
    bool fx = false, fy = false;

    const float2* ipn = ip + (int64_t)(NBUF - 1) * STRIDE2;
    constexpr int GROUPS = NBATCH / NBUF;   // 64

#pragma unroll 1
    for (int g = 0; g < GROUPS; g++) {
#pragma unroll
        for (int p = 0; p < NBUF; p++) {
            // prefetch batch (g*NBUF + p + NBUF-1) into slot (p-1) mod NBUF
            int loadidx = g * NBUF + p + (NBUF - 1);
            const float2* lp = (loadidx < NBATCH) ? ipn : ip;
#pragma unroll
            for (int u = 0; u < UNROLL; u++)
                buf[(p + NBUF - 1) & (NBUF - 1)][u] = __ldcs(lp + u * K2);
            ipn += STRIDE2;

            // compute batch (g*NBUF + p) from slot p
#pragma unroll
            for (int u = 0; u < UNROLL; u++) {
                float2 It = buf[p][u];
                float2 s;
                lif_lane(It.x, c2, uv.x, fx, a.x, n.x, s.x);
                lif_lane(It.y, c2, uv.y, fy, a.y, n.y, s.y);
                __stcs(sp + u * K2, s);
                __stcs(np + u * K2, n);
            }
            sp += STRIDE2; np += STRIDE2;
        }
    }
}

extern "C" void kernel_launch(void* const* d_in, const int* in_sizes, int n_in,
                              void* d_out, int out_size)
{
    const float2* I = (const float2*)d_in[0];
    float2* spikes = (float2*)d_out;
    float2* series = (float2*)((float*)d_out + (int64_t)B_ * L_ * K_);

    dim3 block(64);
    dim3 grid(NTHREADS / 64);   // 128 blocks -> 128 SMs, 2 warps/SM
    MultiLIF_kernel<<<grid, block>>>(I, spikes, series);
}